// round 16
// baseline (speedup 1.0000x reference)
#include <cuda_runtime.h>
#include <cuda_fp16.h>
#include <math.h>

#define NB   64
#define NT   512
#define NIN  512
#define NH   1024
#define GCTA 128

__device__ __half2  g_x16[NB * NT * NIN / 2];
__device__ __half2  g_w16[3 * NH * NIN / 2];
__device__ __half2  g_gi0[(size_t)NB * NT * 3 * NH / 2];  // [t][b][3072] fp16, +bias
__device__ __half2  g_h0[2][NB * NH / 2];
__device__ __half2  g_h1[2][NB * NH / 2];
__device__ unsigned g_bar0, g_bari;

__device__ __forceinline__ float sigm(float x) {
    return __fdividef(1.0f, 1.0f + __expf(-x));
}
__device__ __forceinline__ float ftanh(float x) {
    float xc = fminf(fmaxf(x, -15.0f), 15.0f);
    float e = __expf(2.0f * xc);
    return __fdividef(e - 1.0f, e + 1.0f);
}

__device__ __forceinline__ void mma16816(float* c, unsigned a0, unsigned a1,
                                         unsigned a2, unsigned a3,
                                         unsigned b0, unsigned b1) {
    asm volatile(
        "mma.sync.aligned.m16n8k16.row.col.f32.f16.f16.f32 "
        "{%0,%1,%2,%3},{%4,%5,%6,%7},{%8,%9},{%0,%1,%2,%3};\n"
        : "+f"(c[0]), "+f"(c[1]), "+f"(c[2]), "+f"(c[3])
        : "r"(a0), "r"(a1), "r"(a2), "r"(a3), "r"(b0), "r"(b1));
}

__device__ __forceinline__ void ldsm4(unsigned& r0, unsigned& r1,
                                      unsigned& r2, unsigned& r3,
                                      const __half2* p) {
    unsigned a = (unsigned)__cvta_generic_to_shared(p);
    asm volatile("ldmatrix.sync.aligned.m8n8.x4.shared.b16 {%0,%1,%2,%3}, [%4];"
                 : "=r"(r0), "=r"(r1), "=r"(r2), "=r"(r3) : "r"(a));
}
__device__ __forceinline__ void ldsm2(unsigned& r0, unsigned& r1, const __half2* p) {
    unsigned a = (unsigned)__cvta_generic_to_shared(p);
    asm volatile("ldmatrix.sync.aligned.m8n8.x2.shared.b16 {%0,%1}, [%2];"
                 : "=r"(r0), "=r"(r1) : "r"(a));
}

__device__ __forceinline__ void cp16(unsigned dst, const void* src) {
    asm volatile("cp.async.cg.shared.global [%0], [%1], 16;" :: "r"(dst), "l"(src));
}
__device__ __forceinline__ void cp_commit() { asm volatile("cp.async.commit_group;"); }
template <int N> __device__ __forceinline__ void cp_wait() {
    asm volatile("cp.async.wait_group %0;" :: "n"(N));
}

__device__ __forceinline__ void bar_arrive1(unsigned* bar) {
    __syncthreads();
    if (threadIdx.x == 0) { __threadfence(); atomicAdd(bar, 1u); }
}
__device__ __forceinline__ void bar_wait(unsigned* bar, unsigned target) {
    if (threadIdx.x == 0) {
        unsigned v;
        do {
            asm volatile("ld.global.acquire.gpu.u32 %0, [%1];"
                         : "=r"(v) : "l"(bar) : "memory");
        } while (v < target);
    }
    __syncthreads();
}

__global__ void k_cvt_x(const float4* __restrict__ x) {
    int i = blockIdx.x * 256 + threadIdx.x;
    if (i == 0) { g_bar0 = 0; g_bari = 0; }
    float4 v = x[i];
    g_x16[i * 2]     = __floats2half2_rn(v.x, v.y);
    g_x16[i * 2 + 1] = __floats2half2_rn(v.z, v.w);
}
__global__ void k_cvt_w(const float4* __restrict__ w) {
    int i = blockIdx.x * 256 + threadIdx.x;
    float4 v = w[i];
    g_w16[i * 2]     = __floats2half2_rn(v.x, v.y);
    g_w16[i * 2 + 1] = __floats2half2_rn(v.z, v.w);
}

// ---- phase A: gi0 = x @ Wih0^T + bih0 ----
__global__ void __launch_bounds__(256) k_gi0(const float* __restrict__ bih0) {
    __shared__ __half2 sA[64 * 32];
    __shared__ __half2 sB[64 * 32];
    const int tid = threadIdx.x, wid = tid >> 5, lane = tid & 31;
    const int wm = wid & 3, wn = wid >> 2, gID = lane >> 2, tg = lane & 3;
    const int m0 = blockIdx.y * 64, n0 = blockIdx.x * 64;
    const uint4* A4 = (const uint4*)g_x16;
    const uint4* B4 = (const uint4*)g_w16;
    const int swz = gID << 2;
    float c[4][4] = {};

    for (int p = 0; p < 8; p++) {
        __syncthreads();
#pragma unroll
        for (int rep = 0; rep < 2; rep++) {
            int idx = rep * 256 + tid, r = idx >> 3, cu = idx & 7;
            int base = (cu * 4) ^ ((r & 7) << 2);
            *(uint4*)&sA[r * 32 + base] = A4[(m0 + r) * 64 + p * 8 + cu];
            *(uint4*)&sB[r * 32 + base] = B4[(n0 + r) * 64 + p * 8 + cu];
        }
        __syncthreads();
#pragma unroll
        for (int ks = 0; ks < 4; ks++) {
            int col = ks * 8 + tg;
            int ra0 = (wm * 16 + gID) * 32, ra1 = ra0 + 8 * 32;
            unsigned a0 = *(const unsigned*)&sA[ra0 + (col ^ swz)];
            unsigned a1 = *(const unsigned*)&sA[ra1 + (col ^ swz)];
            unsigned a2 = *(const unsigned*)&sA[ra0 + ((col + 4) ^ swz)];
            unsigned a3 = *(const unsigned*)&sA[ra1 + ((col + 4) ^ swz)];
#pragma unroll
            for (int nt = 0; nt < 4; nt++) {
                int rb = (wn * 32 + nt * 8 + gID) * 32;
                unsigned b0 = *(const unsigned*)&sB[rb + (col ^ swz)];
                unsigned b1 = *(const unsigned*)&sB[rb + ((col + 4) ^ swz)];
                mma16816(c[nt], a0, a1, a2, a3, b0, b1);
            }
        }
    }
    int mrow = m0 + wm * 16 + gID;
#pragma unroll
    for (int nt = 0; nt < 4; nt++) {
        int nc = n0 + wn * 32 + nt * 8 + tg * 2;
        float b0 = bih0[nc], b1 = bih0[nc + 1];
        int bA = mrow >> 9, tA = mrow & 511;
        g_gi0[((size_t)tA * NB + bA) * 1536 + (nc >> 1)] =
            __floats2half2_rn(c[nt][0] + b0, c[nt][1] + b1);
        int m2 = mrow + 8, bB = m2 >> 9, tB = m2 & 511;
        g_gi0[((size_t)tB * NB + bB) * 1536 + (nc >> 1)] =
            __floats2half2_rn(c[nt][2] + b0, c[nt][3] + b1);
    }
}

// ---- persistent recurrence: 12 warps kh(4) x msel(3), K128 groups, 2 slots ----
// bytes: sW 147456 | sA1 2x16KB @147456 | sA2 2x16KB @180224
// overlay (epilogue only): sPre @147456 (18432B), sRed @165888 (18432B)
// state @212992: sH0f 2048, sH1f 2048, sBias 288
#define SW_BYTES  147456
#define STATE_OFF 212992
#define SMEM_BYTES (STATE_OFF + 4384)

__global__ void __launch_bounds__(384, 1) k_gru(
    float* __restrict__ out,
    const float* __restrict__ Whh0, const float* __restrict__ Wih1,
    const float* __restrict__ Whh1,
    const float* __restrict__ bhh0, const float* __restrict__ bih1,
    const float* __restrict__ bhh1,
    const float* __restrict__ encH, int hasFinal) {
    extern __shared__ __align__(16) __half2 smem[];
    char* smc = (char*)smem;
    __half2* sW   = smem;                              // 36864 h2
    float*   sPre = (float*)(smc + SW_BYTES);          // overlay
    float*   sRed = (float*)(smc + SW_BYTES + 18432);  // overlay
    float*   sH0f = (float*)(smc + STATE_OFF);
    float*   sH1f = sH0f + 512;
    float*   sBias = sH1f + 512;

    const int tid = threadIdx.x, wid = tid >> 5, lane = tid & 31;
    const int kh = wid & 3, msel = wid >> 2;   // k-quarter of group, matrix
    const int gID = lane >> 2, tg = lane & 3;
    const int j0 = blockIdx.x * 8;
    const int b = tid >> 2, jj = (tid & 3) * 2;   // valid tid<256
    const int l15 = lane & 15, alo = lane >> 4;
    const int brow = lane & 7, bg = lane >> 4, bcs = (lane >> 3) & 1;
    const unsigned sA1u = (unsigned)__cvta_generic_to_shared(smc + SW_BYTES);
    const unsigned sA2u = sA1u + 32768u;

    const float* Wm[3] = {Whh0, Wih1, Whh1};
    for (int m = 0; m < 3; m++) {
        const float4* W4 = (const float4*)Wm[m];
        for (int i = tid; i < 24 * 256; i += 384) {
            int r = i >> 8, cu = i & 255;
            int grow = (r >> 3) * NH + j0 + (r & 7);
            float4 v = W4[grow * 256 + cu];
            int base = (cu * 2) ^ ((r & 7) << 2);
            __half2* d = &sW[m * 12288 + r * 512 + base];
            d[0] = __floats2half2_rn(v.x, v.y);
            d[1] = __floats2half2_rn(v.z, v.w);
        }
    }
    const float* Bm[3] = {bhh0, bih1, bhh1};
    if (tid < 72) {
        int m = tid / 24, r = tid % 24;
        sBias[tid] = Bm[m][(r >> 3) * NH + j0 + (r & 7)];
    }
    if (tid < 256) {
        float a = encH[b * NH + j0 + jj], c2 = encH[b * NH + j0 + jj + 1];
        sH0f[b * 8 + jj] = a; sH0f[b * 8 + jj + 1] = c2;
        sH1f[b * 8 + jj] = a; sH1f[b * 8 + jj + 1] = c2;
        __half2 hp = __floats2half2_rn(a, c2);
        g_h0[1][b * 512 + ((j0 + jj) >> 1)] = hp;   // h0^{-1}
        g_h1[0][b * 512 + ((j0 + jj) >> 1)] = hp;   // h1^{-2} dummy
        g_h1[1][b * 512 + ((j0 + jj) >> 1)] = hp;   // h1^{-1}
    }
    bar_arrive1(&g_bari);
    bar_wait(&g_bari, GCTA);

    for (int i = 0; i <= NT; i++) {
        __half2 pg0, pg1, pg2;
        if (i < NT && tid < 256) {
            size_t gi = ((size_t)i * NB + b) * 1536 + ((j0 + jj) >> 1);
            pg0 = g_gi0[gi]; pg1 = g_gi0[gi + 512]; pg2 = g_gi0[gi + 1024];
        }
        if (i >= 1) bar_wait(&g_bar0, (unsigned)i * GCTA);  // h0^{i-1}, h1^{i-2}
        const uint4* A1 = (const uint4*)g_h0[(i + 1) & 1];
        const uint4* A2 = (const uint4*)g_h1[i & 1];

        // coalesced K128-group loader: slot = sp&1, both streams
        auto issue = [&](int sp) {
            if (tid < 256) {
                unsigned slotOff = (unsigned)((sp & 1) * 16384);
#pragma unroll
                for (int q = 0; q < 8; q++) {
                    int idx = tid * 4 + (q & 3);
                    int r = idx >> 4, cu = idx & 15;
                    unsigned dst = slotOff + (unsigned)(r * 256 + 16 * (cu ^ (r & 7)));
                    const uint4* src = ((q < 4) ? A1 : A2) + (size_t)r * 128 + sp * 16 + cu;
                    cp16(((q < 4) ? sA1u : sA2u) + dst, src);
                }
            }
            cp_commit();
        };

        float cc[3][4][4] = {};
        issue(0); issue(1);
        const char* sAb0 = smc + SW_BYTES + ((msel == 2) ? 32768 : 0);
        const __half2* wbase = sW + msel * 12288;

#pragma unroll
        for (int s = 0; s < 8; s++) {
            // hoist B loads (weight-resident) before the panel sync
            int t0 = s * 8 + kh * 2;
            unsigned bq[2][4], b2r[2][2];
#pragma unroll
            for (int d = 0; d < 2; d++) {
                int bo = 4 * ((2 * (t0 + d) + bcs) ^ brow);
                ldsm4(bq[d][0], bq[d][1], bq[d][2], bq[d][3],
                      wbase + bg * 4096 + brow * 512 + bo);
                ldsm2(b2r[d][0], b2r[d][1], wbase + 8192 + brow * 512 + bo);
            }
            if (s == 0) cp_wait<1>(); else cp_wait<0>();
            __syncthreads();
            if (s >= 1 && s + 1 < 8) issue(s + 1);   // into slot of group s-1 (drained)

            const char* aB = sAb0 + (s & 1) * 16384;
#pragma unroll
            for (int d = 0; d < 2; d++) {
                int chunk = kh * 4 + d * 2 + alo;
                unsigned af[4][4];
#pragma unroll
                for (int m4 = 0; m4 < 4; m4++) {
                    int r = m4 * 16 + l15;
                    ldsm4(af[m4][0], af[m4][1], af[m4][2], af[m4][3],
                          (const __half2*)(aB + r * 256 + 16 * (chunk ^ (r & 7))));
                }
#pragma unroll
                for (int m4 = 0; m4 < 4; m4++) {
                    mma16816(cc[0][m4], af[m4][0], af[m4][1], af[m4][2], af[m4][3],
                             bq[d][0], bq[d][1]);
                    mma16816(cc[1][m4], af[m4][0], af[m4][1], af[m4][2], af[m4][3],
                             bq[d][2], bq[d][3]);
                    mma16816(cc[2][m4], af[m4][0], af[m4][1], af[m4][2], af[m4][3],
                             b2r[d][0], b2r[d][1]);
                }
            }
        }
        __syncthreads();   // groups drained; overlay region writable

        // 4-way k-reduction in two parallel halves
        int base = msel * 1536, nc = tg * 2;
        if (kh == 3 || kh == 1) {
            float* dst = (kh == 3) ? sPre : sRed;
#pragma unroll
            for (int g = 0; g < 3; g++)
#pragma unroll
                for (int m4 = 0; m4 < 4; m4++) {
                    int r0 = m4 * 16 + gID;
                    *(float2*)&dst[base + r0 * 24 + g * 8 + nc] =
                        make_float2(cc[g][m4][0], cc[g][m4][1]);
                    *(float2*)&dst[base + (r0 + 8) * 24 + g * 8 + nc] =
                        make_float2(cc[g][m4][2], cc[g][m4][3]);
                }
        }
        __syncthreads();
        if (kh == 2 || kh == 0) {
            float* dst = (kh == 2) ? sPre : sRed;
#pragma unroll
            for (int g = 0; g < 3; g++)
#pragma unroll
                for (int m4 = 0; m4 < 4; m4++) {
                    int r0 = m4 * 16 + gID;
                    float2 p0 = *(float2*)&dst[base + r0 * 24 + g * 8 + nc];
                    float2 p1 = *(float2*)&dst[base + (r0 + 8) * 24 + g * 8 + nc];
                    *(float2*)&dst[base + r0 * 24 + g * 8 + nc] =
                        make_float2(cc[g][m4][0] + p0.x, cc[g][m4][1] + p0.y);
                    *(float2*)&dst[base + (r0 + 8) * 24 + g * 8 + nc] =
                        make_float2(cc[g][m4][2] + p1.x, cc[g][m4][3] + p1.y);
                }
        }
        __syncthreads();

        // elementwise: L0 step i, L1 step i-1 (gates = sPre + sRed)
        if (tid < 256) {
            if (i < NT) {
                float gir[2] = {__low2float(pg0), __high2float(pg0)};
                float giz[2] = {__low2float(pg1), __high2float(pg1)};
                float gin[2] = {__low2float(pg2), __high2float(pg2)};
                float h0n[2];
#pragma unroll
                for (int d = 0; d < 2; d++) {
                    int j = jj + d;
                    float ghr = sPre[b * 24 + j]      + sRed[b * 24 + j]      + sBias[j];
                    float ghz = sPre[b * 24 + 8 + j]  + sRed[b * 24 + 8 + j]  + sBias[8 + j];
                    float ghn = sPre[b * 24 + 16 + j] + sRed[b * 24 + 16 + j] + sBias[16 + j];
                    float r = sigm(gir[d] + ghr);
                    float z = sigm(giz[d] + ghz);
                    float n = ftanh(gin[d] + r * ghn);
                    h0n[d] = (1.0f - z) * n + z * sH0f[b * 8 + j];
                }
                sH0f[b * 8 + jj] = h0n[0]; sH0f[b * 8 + jj + 1] = h0n[1];
                g_h0[i & 1][b * 512 + ((j0 + jj) >> 1)] = __floats2half2_rn(h0n[0], h0n[1]);
            }
            if (i >= 1) {
                int t = i - 1;
                float h1n[2];
#pragma unroll
                for (int d = 0; d < 2; d++) {
                    int j = jj + d;
                    float gi1r = sPre[1536 + b * 24 + j]      + sRed[1536 + b * 24 + j]      + sBias[24 + j];
                    float gi1z = sPre[1536 + b * 24 + 8 + j]  + sRed[1536 + b * 24 + 8 + j]  + sBias[32 + j];
                    float gi1n = sPre[1536 + b * 24 + 16 + j] + sRed[1536 + b * 24 + 16 + j] + sBias[40 + j];
                    float gh1r = sPre[3072 + b * 24 + j]      + sRed[3072 + b * 24 + j]      + sBias[48 + j];
                    float gh1z = sPre[3072 + b * 24 + 8 + j]  + sRed[3072 + b * 24 + 8 + j]  + sBias[56 + j];
                    float gh1n = sPre[3072 + b * 24 + 16 + j] + sRed[3072 + b * 24 + 16 + j] + sBias[64 + j];
                    float r = sigm(gi1r + gh1r);
                    float z = sigm(gi1z + gh1z);
                    float n = ftanh(gi1n + r * gh1n);
                    h1n[d] = (1.0f - z) * n + z * sH1f[b * 8 + j];
                }
                sH1f[b * 8 + jj] = h1n[0]; sH1f[b * 8 + jj + 1] = h1n[1];
                g_h1[(i + 1) & 1][b * 512 + ((j0 + jj) >> 1)] = __floats2half2_rn(h1n[0], h1n[1]);
                *(float2*)&out[((size_t)b * NT + t) * NH + j0 + jj] = make_float2(h1n[0], h1n[1]);
                if (hasFinal && t == NT - 1) {
                    float* o2 = out + (size_t)NB * NT * NH;
                    *(float2*)&o2[b * NH + j0 + jj] = make_float2(h1n[0], h1n[1]);
                }
            }
        }
        __syncthreads();
        if (threadIdx.x == 0 && i < NT) {
            __threadfence();
            atomicAdd(&g_bar0, 1u);
        }
    }
}

extern "C" void kernel_launch(void* const* d_in, const int* in_sizes, int n_in,
                              void* d_out, int out_size) {
    const float* x    = (const float*)d_in[0];
    const float* encH = (const float*)d_in[2];
    const float* Wih0 = (const float*)d_in[3];
    const float* Whh0 = (const float*)d_in[4];
    const float* bih0 = (const float*)d_in[5];
    const float* bhh0 = (const float*)d_in[6];
    const float* Wih1 = (const float*)d_in[7];
    const float* Whh1 = (const float*)d_in[8];
    const float* bih1 = (const float*)d_in[9];
    const float* bhh1 = (const float*)d_in[10];
    float* out = (float*)d_out;
    int hasFinal = (out_size >= NB * NT * NH + NB * NH) ? 1 : 0;

    cudaFuncSetAttribute(k_gru, cudaFuncAttributeMaxDynamicSharedMemorySize, SMEM_BYTES);

    k_cvt_x<<<16384, 256>>>((const float4*)x);
    k_cvt_w<<<1536, 256>>>((const float4*)Wih0);
    dim3 g1(48, 512);
    k_gi0<<<g1, 256>>>(bih0);
    k_gru<<<GCTA, 384, SMEM_BYTES>>>(out, Whh0, Wih1, Whh1,
                                     bhh0, bih1, bhh1, encH, hasFinal);
}

// round 17
// speedup vs baseline: 1.3501x; 1.3501x over previous
#include <cuda_runtime.h>
#include <cuda_fp16.h>
#include <math.h>

#define NB   64
#define NT   512
#define NIN  512
#define NH   1024
#define GCTA 128

__device__ __half2  g_x16[NB * NT * NIN / 2];
__device__ __half2  g_w16[3 * NH * NIN / 2];
__device__ __half2  g_gi0[(size_t)NB * NT * 3 * NH / 2];  // [t][b][3072] fp16, +bias
__device__ __half2  g_h0[2][NB * NH / 2];
__device__ __half2  g_h1[2][NB * NH / 2];
__device__ unsigned g_bar0, g_bari;

__device__ __forceinline__ float sigm(float x) {
    return __fdividef(1.0f, 1.0f + __expf(-x));
}
__device__ __forceinline__ float ftanh(float x) {
    float xc = fminf(fmaxf(x, -15.0f), 15.0f);
    float e = __expf(2.0f * xc);
    return __fdividef(e - 1.0f, e + 1.0f);
}

__device__ __forceinline__ void mma16816(float* c, unsigned a0, unsigned a1,
                                         unsigned a2, unsigned a3,
                                         unsigned b0, unsigned b1) {
    asm volatile(
        "mma.sync.aligned.m16n8k16.row.col.f32.f16.f16.f32 "
        "{%0,%1,%2,%3},{%4,%5,%6,%7},{%8,%9},{%0,%1,%2,%3};\n"
        : "+f"(c[0]), "+f"(c[1]), "+f"(c[2]), "+f"(c[3])
        : "r"(a0), "r"(a1), "r"(a2), "r"(a3), "r"(b0), "r"(b1));
}

__device__ __forceinline__ void ldsm4(unsigned& r0, unsigned& r1,
                                      unsigned& r2, unsigned& r3,
                                      const __half2* p) {
    unsigned a = (unsigned)__cvta_generic_to_shared(p);
    asm volatile("ldmatrix.sync.aligned.m8n8.x4.shared.b16 {%0,%1,%2,%3}, [%4];"
                 : "=r"(r0), "=r"(r1), "=r"(r2), "=r"(r3) : "r"(a));
}
__device__ __forceinline__ void ldsm2(unsigned& r0, unsigned& r1, const __half2* p) {
    unsigned a = (unsigned)__cvta_generic_to_shared(p);
    asm volatile("ldmatrix.sync.aligned.m8n8.x2.shared.b16 {%0,%1}, [%2];"
                 : "=r"(r0), "=r"(r1) : "r"(a));
}

__device__ __forceinline__ void cp16(unsigned dst, const void* src) {
    asm volatile("cp.async.cg.shared.global [%0], [%1], 16;" :: "r"(dst), "l"(src));
}
__device__ __forceinline__ void cp_commit() { asm volatile("cp.async.commit_group;"); }
template <int N> __device__ __forceinline__ void cp_wait() {
    asm volatile("cp.async.wait_group %0;" :: "n"(N));
}

__device__ __forceinline__ void bar_arrive1(unsigned* bar) {
    __syncthreads();
    if (threadIdx.x == 0) { __threadfence(); atomicAdd(bar, 1u); }
}
__device__ __forceinline__ void bar_wait(unsigned* bar, unsigned target) {
    if (threadIdx.x == 0) {
        unsigned v;
        do {
            asm volatile("ld.global.acquire.gpu.u32 %0, [%1];"
                         : "=r"(v) : "l"(bar) : "memory");
        } while (v < target);
    }
    __syncthreads();
}

__global__ void k_cvt_x(const float4* __restrict__ x) {
    int i = blockIdx.x * 256 + threadIdx.x;
    if (i == 0) { g_bar0 = 0; g_bari = 0; }
    float4 v = x[i];
    g_x16[i * 2]     = __floats2half2_rn(v.x, v.y);
    g_x16[i * 2 + 1] = __floats2half2_rn(v.z, v.w);
}
__global__ void k_cvt_w(const float4* __restrict__ w) {
    int i = blockIdx.x * 256 + threadIdx.x;
    float4 v = w[i];
    g_w16[i * 2]     = __floats2half2_rn(v.x, v.y);
    g_w16[i * 2 + 1] = __floats2half2_rn(v.z, v.w);
}

// ---- phase A: gi0 = x @ Wih0^T + bih0 ----
__global__ void __launch_bounds__(256) k_gi0(const float* __restrict__ bih0) {
    __shared__ __half2 sA[64 * 32];
    __shared__ __half2 sB[64 * 32];
    const int tid = threadIdx.x, wid = tid >> 5, lane = tid & 31;
    const int wm = wid & 3, wn = wid >> 2, gID = lane >> 2, tg = lane & 3;
    const int m0 = blockIdx.y * 64, n0 = blockIdx.x * 64;
    const uint4* A4 = (const uint4*)g_x16;
    const uint4* B4 = (const uint4*)g_w16;
    const int swz = gID << 2;
    float c[4][4] = {};

    for (int p = 0; p < 8; p++) {
        __syncthreads();
#pragma unroll
        for (int rep = 0; rep < 2; rep++) {
            int idx = rep * 256 + tid, r = idx >> 3, cu = idx & 7;
            int base = (cu * 4) ^ ((r & 7) << 2);
            *(uint4*)&sA[r * 32 + base] = A4[(m0 + r) * 64 + p * 8 + cu];
            *(uint4*)&sB[r * 32 + base] = B4[(n0 + r) * 64 + p * 8 + cu];
        }
        __syncthreads();
#pragma unroll
        for (int ks = 0; ks < 4; ks++) {
            int col = ks * 8 + tg;
            int ra0 = (wm * 16 + gID) * 32, ra1 = ra0 + 8 * 32;
            unsigned a0 = *(const unsigned*)&sA[ra0 + (col ^ swz)];
            unsigned a1 = *(const unsigned*)&sA[ra1 + (col ^ swz)];
            unsigned a2 = *(const unsigned*)&sA[ra0 + ((col + 4) ^ swz)];
            unsigned a3 = *(const unsigned*)&sA[ra1 + ((col + 4) ^ swz)];
#pragma unroll
            for (int nt = 0; nt < 4; nt++) {
                int rb = (wn * 32 + nt * 8 + gID) * 32;
                unsigned b0 = *(const unsigned*)&sB[rb + (col ^ swz)];
                unsigned b1 = *(const unsigned*)&sB[rb + ((col + 4) ^ swz)];
                mma16816(c[nt], a0, a1, a2, a3, b0, b1);
            }
        }
    }
    int mrow = m0 + wm * 16 + gID;
#pragma unroll
    for (int nt = 0; nt < 4; nt++) {
        int nc = n0 + wn * 32 + nt * 8 + tg * 2;
        float b0 = bih0[nc], b1 = bih0[nc + 1];
        int bA = mrow >> 9, tA = mrow & 511;
        g_gi0[((size_t)tA * NB + bA) * 1536 + (nc >> 1)] =
            __floats2half2_rn(c[nt][0] + b0, c[nt][1] + b1);
        int m2 = mrow + 8, bB = m2 >> 9, tB = m2 & 511;
        g_gi0[((size_t)tB * NB + bB) * 1536 + (nc >> 1)] =
            __floats2half2_rn(c[nt][2] + b0, c[nt][3] + b1);
    }
}

// ---- persistent recurrence: 12 warps kh(4) x msel(3), M_w=64 (R14 base) ----
// bytes: sW 147456 | sA1 4x8KB @147456 | sA2 4x8KB @180224
// overlay+extension: sQ[4] quadrants @147456, 4x18432B = 73728B
// state @221184: sH0f 2048, sH1f 2048, sBias 288
#define SW_BYTES  147456
#define STATE_OFF (SW_BYTES + 73728)
#define SMEM_BYTES (STATE_OFF + 4384)

__global__ void __launch_bounds__(384, 1) k_gru(
    float* __restrict__ out,
    const float* __restrict__ Whh0, const float* __restrict__ Wih1,
    const float* __restrict__ Whh1,
    const float* __restrict__ bhh0, const float* __restrict__ bih1,
    const float* __restrict__ bhh1,
    const float* __restrict__ encH, int hasFinal) {
    extern __shared__ __align__(16) __half2 smem[];
    char* smc = (char*)smem;
    __half2* sW   = smem;                              // 36864 h2
    float*   sQ   = (float*)(smc + SW_BYTES);          // 4 quadrants x 4608 f
    float*   sH0f = (float*)(smc + STATE_OFF);
    float*   sH1f = sH0f + 512;
    float*   sBias = sH1f + 512;

    const int tid = threadIdx.x, wid = tid >> 5, lane = tid & 31;
    const int kh = wid & 3, msel = wid >> 2;   // k16-quarter, matrix
    const int gID = lane >> 2, tg = lane & 3;
    const int j0 = blockIdx.x * 8;
    const int b = tid >> 2, jj = (tid & 3) * 2;   // valid tid<256
    const int l15 = lane & 15, alo = lane >> 4;
    const int brow = lane & 7, bg = lane >> 4, bcs = (lane >> 3) & 1;
    const unsigned sA1u = (unsigned)__cvta_generic_to_shared(smc + SW_BYTES);
    const unsigned sA2u = sA1u + 32768u;

    const float* Wm[3] = {Whh0, Wih1, Whh1};
    for (int m = 0; m < 3; m++) {
        const float4* W4 = (const float4*)Wm[m];
        for (int i = tid; i < 24 * 256; i += 384) {
            int r = i >> 8, cu = i & 255;
            int grow = (r >> 3) * NH + j0 + (r & 7);
            float4 v = W4[grow * 256 + cu];
            int base = (cu * 2) ^ ((r & 7) << 2);
            __half2* d = &sW[m * 12288 + r * 512 + base];
            d[0] = __floats2half2_rn(v.x, v.y);
            d[1] = __floats2half2_rn(v.z, v.w);
        }
    }
    const float* Bm[3] = {bhh0, bih1, bhh1};
    if (tid < 72) {
        int m = tid / 24, r = tid % 24;
        sBias[tid] = Bm[m][(r >> 3) * NH + j0 + (r & 7)];
    }
    if (tid < 256) {
        float a = encH[b * NH + j0 + jj], c2 = encH[b * NH + j0 + jj + 1];
        sH0f[b * 8 + jj] = a; sH0f[b * 8 + jj + 1] = c2;
        sH1f[b * 8 + jj] = a; sH1f[b * 8 + jj + 1] = c2;
        __half2 hp = __floats2half2_rn(a, c2);
        g_h0[1][b * 512 + ((j0 + jj) >> 1)] = hp;   // h0^{-1}
        g_h1[0][b * 512 + ((j0 + jj) >> 1)] = hp;   // h1^{-2} dummy
        g_h1[1][b * 512 + ((j0 + jj) >> 1)] = hp;   // h1^{-1}
    }
    bar_arrive1(&g_bari);
    bar_wait(&g_bari, GCTA);

    const char* sAb0 = smc + SW_BYTES + ((msel == 2) ? 32768 : 0);
    const __half2* wbase = sW + msel * 12288;
    const int achk = kh * 2 + alo;   // this lane's A 16B-chunk within row

    for (int i = 0; i <= NT; i++) {
        __half2 pg0, pg1, pg2;
        if (i < NT && tid < 256) {
            size_t gi = ((size_t)i * NB + b) * 1536 + ((j0 + jj) >> 1);
            pg0 = g_gi0[gi]; pg1 = g_gi0[gi + 512]; pg2 = g_gi0[gi + 1024];
        }
        // hoist step-0 B fragments (static weights) above the grid barrier
        unsigned bq0[4], b2r0[2];
        {
            int bo = 4 * ((2 * kh + bcs) ^ brow);
            ldsm4(bq0[0], bq0[1], bq0[2], bq0[3], wbase + bg * 4096 + brow * 512 + bo);
            ldsm2(b2r0[0], b2r0[1], wbase + 8192 + brow * 512 + bo);
        }
        if (i >= 1) bar_wait(&g_bar0, (unsigned)i * GCTA);  // h0^{i-1}, h1^{i-2}
        const uint4* A1 = (const uint4*)g_h0[(i + 1) & 1];
        const uint4* A2 = (const uint4*)g_h1[i & 1];

        // coalesced full-panel loader (K64 of both streams per step)
        auto issue = [&](int p, int buf) {
            if (tid < 256) {
#pragma unroll
                for (int q = 0; q < 4; q++) {
                    int idx = tid * 2 + (q & 1);
                    int r = idx >> 3, cu = idx & 7;
                    unsigned base = (unsigned)((buf * 2048 + r * 32 +
                                    ((cu * 4) ^ ((r & 7) << 2))) * 4);
                    const uint4* src = ((q < 2) ? A1 : A2) + (size_t)r * 128 + p * 8 + cu;
                    cp16(((q < 2) ? sA1u : sA2u) + base, src);
                }
            }
            cp_commit();
        };

        float cc[3][4][4] = {};
        issue(0, 0); issue(1, 1); issue(2, 2);

#pragma unroll
        for (int s = 0; s < 16; s++) {
            // B fragments for step s (loaded pre-barrier for s=0; else here,
            // overlapping the panel sync wait)
            unsigned bq[4], b2r[2];
            if (s == 0) {
#pragma unroll
                for (int q = 0; q < 4; q++) bq[q] = bq0[q];
                b2r[0] = b2r0[0]; b2r[1] = b2r0[1];
            } else {
                int t = s * 4 + kh;
                int bo = 4 * ((2 * t + bcs) ^ brow);
                ldsm4(bq[0], bq[1], bq[2], bq[3], wbase + bg * 4096 + brow * 512 + bo);
                ldsm2(b2r[0], b2r[1], wbase + 8192 + brow * 512 + bo);
            }

            if (s < 14) cp_wait<2>();
            else if (s == 14) cp_wait<1>();
            else cp_wait<0>();
            __syncthreads();
            if (s + 3 < 16) issue(s + 3, (s + 3) & 3);

            const char* aB = sAb0 + (s & 3) * 8192;
            unsigned af[4][4];
#pragma unroll
            for (int m4 = 0; m4 < 4; m4++) {
                int r = m4 * 16 + l15;
                ldsm4(af[m4][0], af[m4][1], af[m4][2], af[m4][3],
                      (const __half2*)(aB + r * 128 + 16 * (achk ^ (r & 7))));
            }
#pragma unroll
            for (int m4 = 0; m4 < 4; m4++) {
                mma16816(cc[0][m4], af[m4][0], af[m4][1], af[m4][2], af[m4][3], bq[0], bq[1]);
                mma16816(cc[1][m4], af[m4][0], af[m4][1], af[m4][2], af[m4][3], bq[2], bq[3]);
                mma16816(cc[2][m4], af[m4][0], af[m4][1], af[m4][2], af[m4][3], b2r[0], b2r[1]);
            }
        }
        __syncthreads();   // panels drained; quadrant region writable

        // single-phase 4-quadrant k-reduction: every warp stores its quadrant
        {
            float* dst = sQ + kh * 4608 + msel * 1536;
            int nc = tg * 2;
#pragma unroll
            for (int g = 0; g < 3; g++)
#pragma unroll
                for (int m4 = 0; m4 < 4; m4++) {
                    int r0 = m4 * 16 + gID;
                    *(float2*)&dst[r0 * 24 + g * 8 + nc] =
                        make_float2(cc[g][m4][0], cc[g][m4][1]);
                    *(float2*)&dst[(r0 + 8) * 24 + g * 8 + nc] =
                        make_float2(cc[g][m4][2], cc[g][m4][3]);
                }
        }
        __syncthreads();

        // elementwise: L0 step i, L1 step i-1 (gates = sum of 4 quadrants)
        if (tid < 256) {
#define GSUM(off) (sQ[off] + sQ[4608 + (off)] + sQ[9216 + (off)] + sQ[13824 + (off)])
            if (i < NT) {
                float gir[2] = {__low2float(pg0), __high2float(pg0)};
                float giz[2] = {__low2float(pg1), __high2float(pg1)};
                float gin[2] = {__low2float(pg2), __high2float(pg2)};
                float h0n[2];
#pragma unroll
                for (int d = 0; d < 2; d++) {
                    int j = jj + d;
                    float ghr = GSUM(b * 24 + j)      + sBias[j];
                    float ghz = GSUM(b * 24 + 8 + j)  + sBias[8 + j];
                    float ghn = GSUM(b * 24 + 16 + j) + sBias[16 + j];
                    float r = sigm(gir[d] + ghr);
                    float z = sigm(giz[d] + ghz);
                    float n = ftanh(gin[d] + r * ghn);
                    h0n[d] = (1.0f - z) * n + z * sH0f[b * 8 + j];
                }
                sH0f[b * 8 + jj] = h0n[0]; sH0f[b * 8 + jj + 1] = h0n[1];
                g_h0[i & 1][b * 512 + ((j0 + jj) >> 1)] = __floats2half2_rn(h0n[0], h0n[1]);
            }
            if (i >= 1) {
                int t = i - 1;
                float h1n[2];
#pragma unroll
                for (int d = 0; d < 2; d++) {
                    int j = jj + d;
                    float gi1r = GSUM(1536 + b * 24 + j)      + sBias[24 + j];
                    float gi1z = GSUM(1536 + b * 24 + 8 + j)  + sBias[32 + j];
                    float gi1n = GSUM(1536 + b * 24 + 16 + j) + sBias[40 + j];
                    float gh1r = GSUM(3072 + b * 24 + j)      + sBias[48 + j];
                    float gh1z = GSUM(3072 + b * 24 + 8 + j)  + sBias[56 + j];
                    float gh1n = GSUM(3072 + b * 24 + 16 + j) + sBias[64 + j];
                    float r = sigm(gi1r + gh1r);
                    float z = sigm(gi1z + gh1z);
                    float n = ftanh(gi1n + r * gh1n);
                    h1n[d] = (1.0f - z) * n + z * sH1f[b * 8 + j];
                }
                sH1f[b * 8 + jj] = h1n[0]; sH1f[b * 8 + jj + 1] = h1n[1];
                g_h1[(i + 1) & 1][b * 512 + ((j0 + jj) >> 1)] = __floats2half2_rn(h1n[0], h1n[1]);
                *(float2*)&out[((size_t)b * NT + t) * NH + j0 + jj] = make_float2(h1n[0], h1n[1]);
                if (hasFinal && t == NT - 1) {
                    float* o2 = out + (size_t)NB * NT * NH;
                    *(float2*)&o2[b * NH + j0 + jj] = make_float2(h1n[0], h1n[1]);
                }
            }
#undef GSUM
        }
        __syncthreads();
        if (threadIdx.x == 0 && i < NT) {
            __threadfence();
            atomicAdd(&g_bar0, 1u);
        }
    }
}

extern "C" void kernel_launch(void* const* d_in, const int* in_sizes, int n_in,
                              void* d_out, int out_size) {
    const float* x    = (const float*)d_in[0];
    const float* encH = (const float*)d_in[2];
    const float* Wih0 = (const float*)d_in[3];
    const float* Whh0 = (const float*)d_in[4];
    const float* bih0 = (const float*)d_in[5];
    const float* bhh0 = (const float*)d_in[6];
    const float* Wih1 = (const float*)d_in[7];
    const float* Whh1 = (const float*)d_in[8];
    const float* bih1 = (const float*)d_in[9];
    const float* bhh1 = (const float*)d_in[10];
    float* out = (float*)d_out;
    int hasFinal = (out_size >= NB * NT * NH + NB * NH) ? 1 : 0;

    cudaFuncSetAttribute(k_gru, cudaFuncAttributeMaxDynamicSharedMemorySize, SMEM_BYTES);

    k_cvt_x<<<16384, 256>>>((const float4*)x);
    k_cvt_w<<<1536, 256>>>((const float4*)Wih0);
    dim3 g1(48, 512);
    k_gi0<<<g1, 256>>>(bih0);
    k_gru<<<GCTA, 384, SMEM_BYTES>>>(out, Whh0, Wih1, Whh1,
                                     bhh0, bih1, bhh1, encH, hasFinal);
}